// round 11
// baseline (speedup 1.0000x reference)
#include <cuda_runtime.h>
#include <cuda_fp16.h>

// FastRotation — warp-autonomous half2 pair tile, v5.
// vs R10: (a) row-per-lane sampling: lane r<25 fixes (j,l), loop varies i;
// coords updated incrementally (3 FADD/point, no base table, no per-point
// 3x3 matvec); output p = i*25+r stays coalesced. (b) staging composes each
// fp16 x-pair (v[x-1],v[x]) in registers via shfl_up and stores ONE STS.32
// per slot (flags for x==0 / x==4 packed in the index table).
// Tile: slot (z,y,xp) at word ((z+1)*7+(y+1))*7+xp, z,y in [-1..5],
// xp in [0..5]; borders zero.

#define KVOL  125
#define ZSTR  49          // words per z-slab (7 rows * 7 words)
#define YSTR  7           // words per row (odd)
#define WORDS 344         // 343 padded to float4 multiple
#define WPB   8           // warps (= volumes) per block
#define TPB   (WPB * 32)

// Staging meta for element m = z*25 + y*5 + x:
//   bits 0..13 : slot word index b = ((z+1)*7 + (y+1))*7 + x
//   bit 14     : x == 0  (prev value is the zero border)
//   bit 15     : x == 4  (also store slot b+1 = (v[4], 0))
#define PB(i,j,l) (((i + 1) * 7 + (j + 1)) * YSTR + (l))
#define MT(i,j,l) (PB(i,j,l) | ((l)==0 ? (1<<14) : 0) | ((l)==4 ? (1<<15) : 0))
#define M5(i,j)  MT(i,j,0), MT(i,j,1), MT(i,j,2), MT(i,j,3), MT(i,j,4)
#define M25(i)   M5(i,0), M5(i,1), M5(i,2), M5(i,3), M5(i,4)
__device__ const int g_meta[128] = { M25(0), M25(1), M25(2), M25(3), M25(4) };

__global__ __launch_bounds__(TPB) void fast_rotation_kernel(
    const float* __restrict__ vol,      // [N,125]
    const float* __restrict__ theta_v,  // [N,3]
    const float* __restrict__ theta,    // [N]
    float* __restrict__ out,            // [N,125]
    int N)
{
    __shared__ __half2 sp[WPB * WORDS];

    const int w    = threadIdx.x >> 5;
    const int lane = threadIdx.x & 31;
    const int n    = blockIdx.x * WPB + w;
    if (n >= N) return;

    __half2* tile = &sp[w * WORDS];

    // Load volume into registers (coalesced)
    const float* vsrc = vol + n * KVOL;
    float vq[4];
    #pragma unroll
    for (int q = 0; q < 4; ++q) {
        const int m = lane + 32 * q;
        vq[q] = (m < KVOL) ? __ldcs(vsrc + m) : 0.0f;
    }

    // Zero-fill tile: 344 half2 = 86 float4
    {
        float4* t4 = (float4*)tile;
        const float4 z4 = make_float4(0.f, 0.f, 0.f, 0.f);
        t4[lane]      = z4;
        t4[lane + 32] = z4;
        if (lane < 86 - 64) t4[lane + 64] = z4;
    }
    __syncwarp();

    // Compose x-pairs in registers and scatter: one STS.32 per slot.
    #pragma unroll
    for (int q = 0; q < 4; ++q) {
        float prev = __shfl_up_sync(0xffffffffu, vq[q], 1);
        const float carry = __shfl_sync(0xffffffffu, vq[q > 0 ? q - 1 : 0], 31);
        if (lane == 0) prev = (q == 0) ? 0.0f : carry;
        const int m = lane + 32 * q;
        if (m < KVOL) {
            const int meta = __ldg(&g_meta[m]);
            const int b = meta & 0x3FFF;
            if (meta & (1 << 14)) prev = 0.0f;      // x == 0: border on the left
            tile[b] = __floats2half2_rn(prev, vq[q]);
            if (meta & (1 << 15))                    // x == 4: right-border slot
                tile[b + 1] = __floats2half2_rn(vq[q], 0.0f);
        }
    }

    // Rodrigues matrix (pre-scaled by 2), redundant per lane. |v|^2 == 1.
    const float tx = theta_v[n * 3 + 0];
    const float ty = theta_v[n * 3 + 1];
    const float tz = theta_v[n * 3 + 2];
    const float inv = rsqrtf(fmaxf(tx * tx + ty * ty + tz * tz, 1e-24f));
    const float vx = tx * inv, vy = ty * inv, vz = tz * inv;
    const float a  = theta[n];
    const float ss = 2.0f * __sinf(a);
    const float cs = 2.0f * (1.0f - __cosf(a));
    const float R00 = 2.0f + cs * (vx * vx - 1.0f);
    const float R01 = -ss * vz + cs * (vx * vy);
    const float R02 =  ss * vy + cs * (vx * vz);
    const float R10 =  ss * vz + cs * (vy * vx);
    const float R11 = 2.0f + cs * (vy * vy - 1.0f);
    const float R12 = -ss * vx + cs * (vy * vz);
    const float R20 = -ss * vy + cs * (vz * vx);
    const float R21 =  ss * vx + cs * (vz * vy);
    const float R22 = 2.0f + cs * (vz * vz - 1.0f);

    __syncwarp();   // tile visible warp-wide

    // Row-per-lane sampling: lane r < 25 fixes (j = r/5, l = r%5); loop over i.
    if (lane < 25) {
        const int j = (lane * 205) >> 10;   // lane / 5
        const int l = lane - 5 * j;
        const float bj = fmaf((float)j, 0.5f, -1.0f);
        const float bl = fmaf((float)l, 0.5f, -1.0f);

        // pixel coords at i=0 (bi = -1): base . (2R) + 2
        float x = fmaf(bj, R10, fmaf(bl, R20, 2.0f)) - R00;
        float y = fmaf(bj, R11, fmaf(bl, R21, 2.0f)) - R01;
        float z = fmaf(bj, R12, fmaf(bl, R22, 2.0f)) - R02;
        const float hx = 0.5f * R00, hy = 0.5f * R01, hz = 0.5f * R02;

        float* dstp = out + n * KVOL + lane;

        #pragma unroll
        for (int i = 0; i < 5; ++i) {
            const int x0 = __float2int_rd(x);
            const int y0 = __float2int_rd(y);
            const int z0 = __float2int_rd(z);
            const float wx = x - (float)x0;
            const float wy = y - (float)y0;
            const float wz = z - (float)z0;

            const bool ok = ((unsigned)(x0 + 1) <= 5u) &
                            ((unsigned)(y0 + 1) <= 5u) &
                            ((unsigned)(z0 + 1) <= 5u);

            float r = 0.0f;
            if (ok) {
                // slot (z0,y0,x0+1): word = (z0+1)*49 + (y0+1)*7 + x0+1
                const int wd = z0 * ZSTR + y0 * YSTR + x0 + (ZSTR + YSTR + 1);
                const __half2 f00 = tile[wd];
                const __half2 f10 = tile[wd + YSTR];
                const __half2 f01 = tile[wd + ZSTR];
                const __half2 f11 = tile[wd + ZSTR + YSTR];

                const __half2 wyb = __float2half2_rn(wy);
                const __half2 wzb = __float2half2_rn(wz);

                const __half2 a0 = __hfma2(__hsub2(f10, f00), wyb, f00);
                const __half2 a1 = __hfma2(__hsub2(f11, f01), wyb, f01);
                const __half2 g  = __hfma2(__hsub2(a1, a0), wzb, a0);

                const float2 gf = __half22float2(g);
                r = fmaf(wx, gf.y - gf.x, gf.x);
            }
            dstp[i * 25] = r;

            x += hx; y += hy; z += hz;
        }
    }
}

extern "C" void kernel_launch(void* const* d_in, const int* in_sizes, int n_in,
                              void* d_out, int out_size)
{
    const float* vol     = (const float*)d_in[0];  // input_filter [N,5,5,5]
    const float* theta_v = (const float*)d_in[1];  // [N,3]
    const float* theta   = (const float*)d_in[2];  // [N]
    float* out = (float*)d_out;

    const int N = in_sizes[2];                     // theta has N elements
    const int blocks = (N + WPB - 1) / WPB;
    fast_rotation_kernel<<<blocks, TPB>>>(vol, theta_v, theta, out, N);
}

// round 12
// speedup vs baseline: 1.0003x; 1.0003x over previous
#include <cuda_runtime.h>
#include <cuda_fp16.h>

// FastRotation — warp-autonomous half2 pair tile, v6 = R10 sampling + R11 staging.
// One warp per 5x5x5 volume.
//  - Staging: fp16 x-pairs (v[x-1],v[x]) composed in registers via shfl_up,
//    ONE STS.32 per tile slot (flags for x==0 / x==4 in the index table).
//  - Sampling: per-point mapping p = lane + 32q (full lane efficiency),
//    packed-fp16 base-coord table (LDG.64), a + w*(b-a) lerps in HFMA2.
// Tile: slot (z,y,xp) at word ((z+1)*7+(y+1))*7+xp holds fp16 x-pair
// (v[z][y][xp-1], v[z][y][xp]); z,y in [-1..5], xp in [0..5]; borders zero.

#define KVOL  125
#define ZSTR  49          // words per z-slab (7 rows * 7 words)
#define YSTR  7           // words per row (odd)
#define WORDS 344         // 343 padded to float4 multiple
#define WPB   8           // warps (= volumes) per block
#define TPB   (WPB * 32)

// fp16 bit patterns for lattice coord c = 0.5*idx - 1, idx in 0..4
#define HP(i) ((i)==0 ? 0xBC00u : (i)==1 ? 0xB800u : (i)==2 ? 0x0000u : \
               (i)==3 ? 0x3800u : 0x3C00u)
// Packed base for point p = i*25 + j*5 + l : u.x = half(bi)|half(bj)<<16, u.y = half(bl)
#define UV(i,j,l) { HP(i) | (HP(j) << 16), HP(l) }
#define U5(i,j)  UV(i,j,0), UV(i,j,1), UV(i,j,2), UV(i,j,3), UV(i,j,4)
#define U25(i)   U5(i,0), U5(i,1), U5(i,2), U5(i,3), U5(i,4)
__device__ const uint2 g_bh[128] = { U25(0), U25(1), U25(2), U25(3), U25(4) };

// Staging meta for element m = z*25 + y*5 + x:
//   bits 0..13 : slot word index b = ((z+1)*7 + (y+1))*7 + x
//   bit 14     : x == 0  (left neighbor is the zero border)
//   bit 15     : x == 4  (also store slot b+1 = (v[4], 0))
#define PB(i,j,l) (((i + 1) * 7 + (j + 1)) * YSTR + (l))
#define MT(i,j,l) (PB(i,j,l) | ((l)==0 ? (1<<14) : 0) | ((l)==4 ? (1<<15) : 0))
#define M5(i,j)  MT(i,j,0), MT(i,j,1), MT(i,j,2), MT(i,j,3), MT(i,j,4)
#define M25(i)   M5(i,0), M5(i,1), M5(i,2), M5(i,3), M5(i,4)
__device__ const int g_meta[128] = { M25(0), M25(1), M25(2), M25(3), M25(4) };

__global__ __launch_bounds__(TPB) void fast_rotation_kernel(
    const float* __restrict__ vol,      // [N,125]
    const float* __restrict__ theta_v,  // [N,3]
    const float* __restrict__ theta,    // [N]
    float* __restrict__ out,            // [N,125]
    int N)
{
    __shared__ __half2 sp[WPB * WORDS];

    const int w    = threadIdx.x >> 5;
    const int lane = threadIdx.x & 31;
    const int n    = blockIdx.x * WPB + w;
    if (n >= N) return;

    __half2* tile = &sp[w * WORDS];

    // Load volume into registers (coalesced); needed upfront for carry shfl.
    const float* vsrc = vol + n * KVOL;
    float vq[4];
    #pragma unroll
    for (int q = 0; q < 4; ++q) {
        const int m = lane + 32 * q;
        vq[q] = (m < KVOL) ? __ldcs(vsrc + m) : 0.0f;
    }

    // Zero-fill tile: 344 half2 = 86 float4
    {
        float4* t4 = (float4*)tile;
        const float4 z4 = make_float4(0.f, 0.f, 0.f, 0.f);
        t4[lane]      = z4;
        t4[lane + 32] = z4;
        if (lane < 86 - 64) t4[lane + 64] = z4;
    }
    __syncwarp();

    // Compose x-pairs in registers, scatter one STS.32 per slot.
    #pragma unroll
    for (int q = 0; q < 4; ++q) {
        float prev = __shfl_up_sync(0xffffffffu, vq[q], 1);
        const float carry = __shfl_sync(0xffffffffu, vq[q > 0 ? q - 1 : 0], 31);
        if (lane == 0) prev = (q == 0) ? 0.0f : carry;
        const int m = lane + 32 * q;
        if (m < KVOL) {
            const int meta = __ldg(&g_meta[m]);
            const int b = meta & 0x3FFF;
            if (meta & (1 << 14)) prev = 0.0f;      // x == 0: zero border left
            tile[b] = __floats2half2_rn(prev, vq[q]);
            if (meta & (1 << 15))                    // x == 4: right-border slot
                tile[b + 1] = __floats2half2_rn(vq[q], 0.0f);
        }
    }

    // Rodrigues matrix (pre-scaled by 2), redundant per lane. |v|^2 == 1.
    const float tx = theta_v[n * 3 + 0];
    const float ty = theta_v[n * 3 + 1];
    const float tz = theta_v[n * 3 + 2];
    const float inv = rsqrtf(fmaxf(tx * tx + ty * ty + tz * tz, 1e-24f));
    const float vx = tx * inv, vy = ty * inv, vz = tz * inv;
    const float a  = theta[n];
    const float ss = 2.0f * __sinf(a);
    const float cs = 2.0f * (1.0f - __cosf(a));
    const float R00 = 2.0f + cs * (vx * vx - 1.0f);
    const float R01 = -ss * vz + cs * (vx * vy);
    const float R02 =  ss * vy + cs * (vx * vz);
    const float R10 =  ss * vz + cs * (vy * vx);
    const float R11 = 2.0f + cs * (vy * vy - 1.0f);
    const float R12 = -ss * vx + cs * (vy * vz);
    const float R20 = -ss * vy + cs * (vz * vx);
    const float R21 =  ss * vx + cs * (vz * vy);
    const float R22 = 2.0f + cs * (vz * vz - 1.0f);

    __syncwarp();   // tile visible warp-wide

    float* dst = out + n * KVOL;

    #pragma unroll
    for (int q = 0; q < 4; ++q) {
        const int p = lane + 32 * q;
        if (p < KVOL) {
            const uint2 u = __ldg(&g_bh[p]);
            const __half2 hij = *reinterpret_cast<const __half2*>(&u.x);
            const float2 bij  = __half22float2(hij);
            const float  bl   = __half2float(*reinterpret_cast<const __half*>(&u.y));

            // pixel coords: (grid + 1) * 2 = base . (2R) + 2
            const float x = fmaf(bij.x, R00, fmaf(bij.y, R10, fmaf(bl, R20, 2.0f)));
            const float y = fmaf(bij.x, R01, fmaf(bij.y, R11, fmaf(bl, R21, 2.0f)));
            const float z = fmaf(bij.x, R02, fmaf(bij.y, R12, fmaf(bl, R22, 2.0f)));

            const int x0 = __float2int_rd(x);
            const int y0 = __float2int_rd(y);
            const int z0 = __float2int_rd(z);
            const float wx = x - (float)x0;
            const float wy = y - (float)y0;
            const float wz = z - (float)z0;

            // In-range iff base cell in [-1,4] per axis; else exact zero.
            const bool ok = ((unsigned)(x0 + 1) <= 5u) &
                            ((unsigned)(y0 + 1) <= 5u) &
                            ((unsigned)(z0 + 1) <= 5u);

            float r = 0.0f;
            if (ok) {
                // slot (z0,y0,x0+1): word = (z0+1)*49 + (y0+1)*7 + x0+1
                const int wd = z0 * ZSTR + y0 * YSTR + x0 + (ZSTR + YSTR + 1);
                const __half2 f00 = tile[wd];
                const __half2 f10 = tile[wd + YSTR];
                const __half2 f01 = tile[wd + ZSTR];
                const __half2 f11 = tile[wd + ZSTR + YSTR];

                const __half2 wyb = __float2half2_rn(wy);
                const __half2 wzb = __float2half2_rn(wz);

                const __half2 a0 = __hfma2(__hsub2(f10, f00), wyb, f00);
                const __half2 a1 = __hfma2(__hsub2(f11, f01), wyb, f01);
                const __half2 g  = __hfma2(__hsub2(a1, a0), wzb, a0);

                const float2 gf = __half22float2(g);
                r = fmaf(wx, gf.y - gf.x, gf.x);
            }
            dst[p] = r;
        }
    }
}

extern "C" void kernel_launch(void* const* d_in, const int* in_sizes, int n_in,
                              void* d_out, int out_size)
{
    const float* vol     = (const float*)d_in[0];  // input_filter [N,5,5,5]
    const float* theta_v = (const float*)d_in[1];  // [N,3]
    const float* theta   = (const float*)d_in[2];  // [N]
    float* out = (float*)d_out;

    const int N = in_sizes[2];                     // theta has N elements
    const int blocks = (N + WPB - 1) / WPB;
    fast_rotation_kernel<<<blocks, TPB>>>(vol, theta_v, theta, out, N);
}